// round 1
// baseline (speedup 1.0000x reference)
#include <cuda_runtime.h>
#include <cuda_bf16.h>
#include <cstdint>

#define NNODES 100000
#define NEDGES 300000
#define ETOT   (NEDGES + NNODES)
#define GDIM   2048
#define HIDDIM 256
#define EDIM   64
#define NLAYER 3

// ---------------- static device scratch (no allocation allowed) ----------------
__device__ float g_bufA[(size_t)NNODES * HIDDIM];
__device__ float g_bufB[(size_t)NNODES * HIDDIM];
__device__ float g_xl[(size_t)NNODES * HIDDIM];
__device__ float g_xr[(size_t)NNODES * HIDDIM];
__device__ float g_eproj[(size_t)NEDGES * HIDDIM];
__device__ float g_logits[(size_t)ETOT * 4];   // logits, then p (in-place)
__device__ float g_lmax[(size_t)NNODES * 4];
__device__ float g_denom[(size_t)NNODES * 4];
__device__ float g_eloop[HIDDIM];
__device__ float g_esum[EDIM];
__device__ float g_gsum[(size_t)GDIM * HIDDIM];
__device__ float g_gcnt[GDIM];

// ---------------- helpers ----------------
__device__ __forceinline__ void red4(float* p, float a, float b, float c, float d) {
    asm volatile("red.global.add.v4.f32 [%0], {%1,%2,%3,%4};"
                 :: "l"(p), "f"(a), "f"(b), "f"(c), "f"(d) : "memory");
}

// float atomic max: signed-int max for >=0, unsigned-int min for <0.
// Monotone in float order given init bits 0xFFFFFFFF.
__device__ __forceinline__ void atomicMaxFloat(float* addr, float val) {
    if (val >= 0.0f) atomicMax((int*)addr, __float_as_int(val));
    else             atomicMin((unsigned int*)addr, __float_as_uint(val));
}

// ---------------- GEMM: C[M,256] = A[M,K] @ W[K,256] (+bias) ----------------
// 64x64 tile, 256 threads, 4x4 per thread, BK=16.
template<int K>
__global__ __launch_bounds__(256)
void gemm_bias_kernel(const float* __restrict__ A, const float* __restrict__ W,
                      const float* __restrict__ bias, float* __restrict__ C, int M) {
    __shared__ float As[16][64];
    __shared__ float Ws[16][64];
    const int tid = threadIdx.x;
    const int row0 = blockIdx.y * 64;
    const int col0 = blockIdx.x * 64;
    const int tx = tid & 15, ty = tid >> 4;
    const int ar = tid >> 2, akv = tid & 3;      // A load: row, which float4 of 16
    const int wk = tid >> 4, wnv = tid & 15;     // W load: k-row, float4 within 64 cols

    float acc[4][4];
#pragma unroll
    for (int i = 0; i < 4; i++)
#pragma unroll
        for (int j = 0; j < 4; j++) acc[i][j] = 0.0f;

    for (int k0 = 0; k0 < K; k0 += 16) {
        float4 av = make_float4(0.f, 0.f, 0.f, 0.f);
        int arow = row0 + ar;
        if (arow < M) av = *(const float4*)(A + (size_t)arow * K + k0 + akv * 4);
        As[akv * 4 + 0][ar] = av.x;
        As[akv * 4 + 1][ar] = av.y;
        As[akv * 4 + 2][ar] = av.z;
        As[akv * 4 + 3][ar] = av.w;
        float4 wv = *(const float4*)(W + (size_t)(k0 + wk) * 256 + col0 + wnv * 4);
        *(float4*)&Ws[wk][wnv * 4] = wv;
        __syncthreads();
#pragma unroll
        for (int kk = 0; kk < 16; kk++) {
            float4 a = *(float4*)&As[kk][ty * 4];
            float4 b = *(float4*)&Ws[kk][tx * 4];
            acc[0][0] = fmaf(a.x, b.x, acc[0][0]); acc[0][1] = fmaf(a.x, b.y, acc[0][1]);
            acc[0][2] = fmaf(a.x, b.z, acc[0][2]); acc[0][3] = fmaf(a.x, b.w, acc[0][3]);
            acc[1][0] = fmaf(a.y, b.x, acc[1][0]); acc[1][1] = fmaf(a.y, b.y, acc[1][1]);
            acc[1][2] = fmaf(a.y, b.z, acc[1][2]); acc[1][3] = fmaf(a.y, b.w, acc[1][3]);
            acc[2][0] = fmaf(a.z, b.x, acc[2][0]); acc[2][1] = fmaf(a.z, b.y, acc[2][1]);
            acc[2][2] = fmaf(a.z, b.z, acc[2][2]); acc[2][3] = fmaf(a.z, b.w, acc[2][3]);
            acc[3][0] = fmaf(a.w, b.x, acc[3][0]); acc[3][1] = fmaf(a.w, b.y, acc[3][1]);
            acc[3][2] = fmaf(a.w, b.z, acc[3][2]); acc[3][3] = fmaf(a.w, b.w, acc[3][3]);
        }
        __syncthreads();
    }

    float4 bv = make_float4(0.f, 0.f, 0.f, 0.f);
    if (bias) bv = *(const float4*)(bias + col0 + tx * 4);
#pragma unroll
    for (int i = 0; i < 4; i++) {
        int r = row0 + ty * 4 + i;
        if (r < M) {
            float4 o;
            o.x = acc[i][0] + bv.x; o.y = acc[i][1] + bv.y;
            o.z = acc[i][2] + bv.z; o.w = acc[i][3] + bv.w;
            *(float4*)(C + (size_t)r * 256 + col0 + tx * 4) = o;
        }
    }
}

// ---------------- edge_attr column sums (for self-loop mean feature) ----------------
__global__ void esum_kernel(const float* __restrict__ ea) {
    int col = threadIdx.x & 63;
    int rowsPerBlk = blockDim.x >> 6;
    int r0 = blockIdx.x * rowsPerBlk + (threadIdx.x >> 6);
    int rstride = gridDim.x * rowsPerBlk;
    float s = 0.0f;
    for (int r = r0; r < NEDGES; r += rstride) s += ea[(size_t)r * EDIM + col];
    atomicAdd(&g_esum[col], s);
}

// eloop[j] = (esum/E) @ We[:, j]
__global__ void eloop_kernel(const float* __restrict__ We) {
    int j = threadIdx.x;
    const float inv = 1.0f / (float)NEDGES;
    float acc = 0.0f;
#pragma unroll
    for (int k = 0; k < EDIM; k++) acc = fmaf(g_esum[k] * inv, We[k * 256 + j], acc);
    g_eloop[j] = acc;
}

// ---------------- logits + segment max (one warp per edge) ----------------
__global__ void logits_kernel(const int* __restrict__ src, const int* __restrict__ dst,
                              const float* __restrict__ att) {
    int gt = blockIdx.x * blockDim.x + threadIdx.x;
    int e = gt >> 5, lane = gt & 31;
    if (e >= ETOT) return;
    int s, d; const float* ep;
    if (e < NEDGES) { s = src[e]; d = dst[e]; ep = g_eproj + (size_t)e * 256; }
    else            { s = e - NEDGES; d = s;  ep = g_eloop; }
    int off = lane * 8;
    const float4* pl = (const float4*)(g_xl + (size_t)s * 256 + off);
    const float4* pr = (const float4*)(g_xr + (size_t)d * 256 + off);
    const float4* pe = (const float4*)(ep + off);
    const float4* pa = (const float4*)(att + off);
    float acc = 0.0f;
#pragma unroll
    for (int q = 0; q < 2; q++) {
        float4 a = pl[q], b = pr[q], c = pe[q], w = pa[q];
        float m;
        m = a.x + b.x + c.x; m = fmaxf(m, 0.2f * m); acc = fmaf(m, w.x, acc);
        m = a.y + b.y + c.y; m = fmaxf(m, 0.2f * m); acc = fmaf(m, w.y, acc);
        m = a.z + b.z + c.z; m = fmaxf(m, 0.2f * m); acc = fmaf(m, w.z, acc);
        m = a.w + b.w + c.w; m = fmaxf(m, 0.2f * m); acc = fmaf(m, w.w, acc);
    }
    acc += __shfl_down_sync(0xffffffffu, acc, 4, 8);
    acc += __shfl_down_sync(0xffffffffu, acc, 2, 8);
    acc += __shfl_down_sync(0xffffffffu, acc, 1, 8);
    if ((lane & 7) == 0) {
        int h = lane >> 3;
        g_logits[(size_t)e * 4 + h] = acc;
        atomicMaxFloat(&g_lmax[(size_t)d * 4 + h], acc);
    }
}

// ---------------- exp + segment sum ----------------
__global__ void expsum_kernel(const int* __restrict__ dst) {
    int idx = blockIdx.x * blockDim.x + threadIdx.x;
    if (idx >= ETOT * 4) return;
    int e = idx >> 2, h = idx & 3;
    int d = (e < NEDGES) ? dst[e] : e - NEDGES;
    float p = __expf(g_logits[idx] - g_lmax[(size_t)d * 4 + h]);
    g_logits[idx] = p;
    atomicAdd(&g_denom[(size_t)d * 4 + h], p);
}

// ---------------- weighted scatter: xn[dst] += xl[src] * alpha ----------------
__global__ void scatter_kernel(const int* __restrict__ src, const int* __restrict__ dst,
                               float* __restrict__ xn) {
    int gt = blockIdx.x * blockDim.x + threadIdx.x;
    int e = gt >> 5, lane = gt & 31;
    if (e >= ETOT) return;
    int s, d;
    if (e < NEDGES) { s = src[e]; d = dst[e]; }
    else            { s = e - NEDGES; d = s; }
    int h = lane >> 3;
    float p  = g_logits[(size_t)e * 4 + h];
    float dn = g_denom[(size_t)d * 4 + h];
    float alpha = p / (dn + 1e-16f);
    const float4* xs = (const float4*)(g_xl + (size_t)s * 256) + lane * 2;
    float4 v0 = xs[0], v1 = xs[1];
    float* base = xn + (size_t)d * 256 + lane * 8;
    red4(base,     v0.x * alpha, v0.y * alpha, v0.z * alpha, v0.w * alpha);
    red4(base + 4, v1.x * alpha, v1.y * alpha, v1.z * alpha, v1.w * alpha);
}

// ---------------- relu(x + bias) in place ----------------
__global__ void relu_bias_kernel(float* __restrict__ x, const float* __restrict__ bias) {
    int i = blockIdx.x * blockDim.x + threadIdx.x;   // over N*64 float4s
    if (i >= NNODES * 64) return;
    float4 v = ((float4*)x)[i];
    float4 b = *(const float4*)(bias + (i & 63) * 4);
    v.x = fmaxf(v.x + b.x, 0.f); v.y = fmaxf(v.y + b.y, 0.f);
    v.z = fmaxf(v.z + b.z, 0.f); v.w = fmaxf(v.w + b.w, 0.f);
    ((float4*)x)[i] = v;
}

// ---------------- global mean pool (warp per node) ----------------
__global__ void pool_kernel(const int* __restrict__ batch, const float* __restrict__ xf) {
    int gt = blockIdx.x * blockDim.x + threadIdx.x;
    int node = gt >> 5, lane = gt & 31;
    if (node >= NNODES) return;
    int g = batch[node];
    const float4* xs = (const float4*)(xf + (size_t)node * 256) + lane * 2;
    float4 v0 = xs[0], v1 = xs[1];
    float* base = g_gsum + (size_t)g * 256 + lane * 8;
    red4(base,     v0.x, v0.y, v0.z, v0.w);
    red4(base + 4, v1.x, v1.y, v1.z, v1.w);
    if (lane == 0) atomicAdd(&g_gcnt[g], 1.0f);
}

// ---------------- final MLP: block per graph ----------------
__global__ __launch_bounds__(128)
void mlp_kernel(const float* __restrict__ Wp1, const float* __restrict__ bp1,
                const float* __restrict__ Wp2, const float* __restrict__ bp2,
                float* __restrict__ out) {
    int g = blockIdx.x;
    __shared__ float pooled[256];
    __shared__ float partial[4];
    float cnt = fmaxf(g_gcnt[g], 1.0f);
    for (int i = threadIdx.x; i < 256; i += 128)
        pooled[i] = g_gsum[(size_t)g * 256 + i] / cnt;
    __syncthreads();
    int j = threadIdx.x;
    float acc = bp1[j];
#pragma unroll 8
    for (int k = 0; k < 256; k++) acc = fmaf(pooled[k], Wp1[k * 128 + j], acc);
    float h = fmaxf(acc, 0.0f) * Wp2[j];
#pragma unroll
    for (int o = 16; o; o >>= 1) h += __shfl_down_sync(0xffffffffu, h, o);
    if ((threadIdx.x & 31) == 0) partial[threadIdx.x >> 5] = h;
    __syncthreads();
    if (threadIdx.x == 0)
        out[g] = partial[0] + partial[1] + partial[2] + partial[3] + bp2[0];
}

// ---------------- launcher ----------------
extern "C" void kernel_launch(void* const* d_in, const int* in_sizes, int n_in,
                              void* d_out, int out_size) {
    const float* x     = (const float*)d_in[0];
    const int*   ei    = (const int*)  d_in[1];
    const float* ea    = (const float*)d_in[2];
    const int*   batch = (const int*)  d_in[3];
    const float* Wl    = (const float*)d_in[4];
    const float* bl    = (const float*)d_in[5];
    const float* Wr    = (const float*)d_in[6];
    const float* br    = (const float*)d_in[7];
    const float* We    = (const float*)d_in[8];
    const float* att   = (const float*)d_in[9];
    const float* bias  = (const float*)d_in[10];
    const float* Wp1   = (const float*)d_in[11];
    const float* bp1   = (const float*)d_in[12];
    const float* Wp2   = (const float*)d_in[13];
    const float* bp2   = (const float*)d_in[14];
    float* out = (float*)d_out;
    const int* src = ei;
    const int* dst = ei + NEDGES;

    float *bufA, *bufB, *xl, *xr, *eproj, *lmax, *denom, *esum, *gsum, *gcnt;
    cudaGetSymbolAddress((void**)&bufA,  g_bufA);
    cudaGetSymbolAddress((void**)&bufB,  g_bufB);
    cudaGetSymbolAddress((void**)&xl,    g_xl);
    cudaGetSymbolAddress((void**)&xr,    g_xr);
    cudaGetSymbolAddress((void**)&eproj, g_eproj);
    cudaGetSymbolAddress((void**)&lmax,  g_lmax);
    cudaGetSymbolAddress((void**)&denom, g_denom);
    cudaGetSymbolAddress((void**)&esum,  g_esum);
    cudaGetSymbolAddress((void**)&gsum,  g_gsum);
    cudaGetSymbolAddress((void**)&gcnt,  g_gcnt);

    cudaMemsetAsync(esum, 0, EDIM * sizeof(float));
    esum_kernel<<<512, 256>>>(ea);

    const float* xcur = x;
    for (int l = 0; l < NLAYER; l++) {
        float* xn = (l & 1) ? bufB : bufA;
        dim3 gN(4, (NNODES + 63) / 64);
        gemm_bias_kernel<256><<<gN, 256>>>(xcur, Wl + (size_t)l * 256 * 256, bl + l * 256, xl, NNODES);
        gemm_bias_kernel<256><<<gN, 256>>>(xcur, Wr + (size_t)l * 256 * 256, br + l * 256, xr, NNODES);
        dim3 gE(4, (NEDGES + 63) / 64);
        gemm_bias_kernel<64><<<gE, 256>>>(ea, We + (size_t)l * 64 * 256, nullptr, eproj, NEDGES);
        eloop_kernel<<<1, 256>>>(We + (size_t)l * 64 * 256);

        cudaMemsetAsync(lmax, 0xFF, (size_t)NNODES * 4 * sizeof(float));
        cudaMemsetAsync(denom, 0, (size_t)NNODES * 4 * sizeof(float));
        cudaMemsetAsync(xn, 0, (size_t)NNODES * 256 * sizeof(float));

        logits_kernel<<<(ETOT * 32) / 256, 256>>>(src, dst, att + l * 256);
        expsum_kernel<<<(ETOT * 4) / 256, 256>>>(dst);
        scatter_kernel<<<(ETOT * 32) / 256, 256>>>(src, dst, xn);
        relu_bias_kernel<<<(NNODES * 64) / 256, 256>>>(xn, bias + l * 256);
        xcur = xn;
    }

    cudaMemsetAsync(gsum, 0, (size_t)GDIM * 256 * sizeof(float));
    cudaMemsetAsync(gcnt, 0, GDIM * sizeof(float));
    pool_kernel<<<(NNODES * 32 + 255) / 256, 256>>>(batch, xcur);
    mlp_kernel<<<GDIM, 128>>>(Wp1, bp1, Wp2, bp2, out);
}

// round 3
// speedup vs baseline: 1.8269x; 1.8269x over previous
#include <cuda_runtime.h>
#include <cuda_bf16.h>
#include <cstdint>

#define NNODES 100000
#define NEDGES 300000
#define ETOT   (NEDGES + NNODES)
#define GDIM   2048
#define HIDDIM 256
#define EDIM   64
#define NLAYER 3

// ---------------- static device scratch ----------------
__device__ float g_bufA[(size_t)NNODES * HIDDIM];
__device__ float g_bufB[(size_t)NNODES * HIDDIM];
__device__ float g_xl[(size_t)NNODES * HIDDIM];
__device__ float g_xr[(size_t)NNODES * HIDDIM];
__device__ float g_eproj[(size_t)NEDGES * HIDDIM];
__device__ float g_logits[(size_t)ETOT * 4];   // stores p = exp(logit)
__device__ float g_denom[(size_t)NNODES * 4];
__device__ float g_eloop[HIDDIM];
__device__ float g_esum[EDIM];
__device__ float g_gsum[(size_t)GDIM * HIDDIM];
__device__ float g_gcnt[GDIM];

// ---------------- helpers ----------------
__device__ __forceinline__ void red4(float* p, float a, float b, float c, float d) {
    asm volatile("red.global.add.v4.f32 [%0], {%1,%2,%3,%4};"
                 :: "l"(p), "f"(a), "f"(b), "f"(c), "f"(d) : "memory");
}

__device__ __forceinline__ void mma_tf32(float* c, const uint32_t* a, const uint32_t* b) {
    asm volatile("mma.sync.aligned.m16n8k8.row.col.f32.tf32.tf32.f32 "
                 "{%0,%1,%2,%3}, {%4,%5,%6,%7}, {%8,%9}, {%0,%1,%2,%3};"
                 : "+f"(c[0]), "+f"(c[1]), "+f"(c[2]), "+f"(c[3])
                 : "r"(a[0]), "r"(a[1]), "r"(a[2]), "r"(a[3]), "r"(b[0]), "r"(b[1]));
}

// ---------------- tf32 tensor-core GEMM: C[M,256] = A[M,K] @ W[K,256] (+bias) ----------------
// CTA tile 128x128, BK=32. 8 warps as 4x2; each warp 32 rows x 64 cols
// (2 m-tiles x 8 n-tiles of m16n8k8).
template<int K, bool HASBIAS>
__global__ __launch_bounds__(256)
void gemm_mma(const float* __restrict__ A, const float* __restrict__ W,
              const float* __restrict__ bias, float* __restrict__ C, int M) {
    __shared__ __align__(16) float As[128][36];   // [m][k], pad 4
    __shared__ __align__(16) float Bs[32][136];   // [k][n], pad 8
    const int tid = threadIdx.x, warp = tid >> 5, lane = tid & 31;
    const int warp_m = warp & 3, warp_n = warp >> 2;
    const int row0 = blockIdx.x * 128, col0 = blockIdx.y * 128;
    const int lq = lane >> 2, lr = lane & 3;

    float acc[2][8][4];
#pragma unroll
    for (int mt = 0; mt < 2; mt++)
#pragma unroll
        for (int nt = 0; nt < 8; nt++)
#pragma unroll
            for (int i = 0; i < 4; i++) acc[mt][nt][i] = 0.0f;

    for (int k0 = 0; k0 < K; k0 += 32) {
#pragma unroll
        for (int i = 0; i < 4; i++) {
            int idx = tid + i * 256;          // 0..1023 float4s of A tile
            int r = idx >> 3, q = idx & 7;
            int ar = row0 + r; if (ar >= M) ar = M - 1;
            *(float4*)&As[r][q * 4] = *(const float4*)(A + (size_t)ar * K + k0 + q * 4);
        }
#pragma unroll
        for (int i = 0; i < 4; i++) {
            int idx = tid + i * 256;          // 0..1023 float4s of B tile
            int r = idx >> 5, q = idx & 31;
            *(float4*)&Bs[r][q * 4] = *(const float4*)(W + (size_t)(k0 + r) * 256 + col0 + q * 4);
        }
        __syncthreads();
#pragma unroll
        for (int ks = 0; ks < 4; ks++) {
            const int kb = ks * 8;
            uint32_t bf[8][2];
            const int brow = kb + lr, bcol = warp_n * 64 + lq;
#pragma unroll
            for (int nt = 0; nt < 8; nt++) {
                bf[nt][0] = __float_as_uint(Bs[brow][bcol + nt * 8]);
                bf[nt][1] = __float_as_uint(Bs[brow + 4][bcol + nt * 8]);
            }
#pragma unroll
            for (int mt = 0; mt < 2; mt++) {
                uint32_t af[4];
                const int arow = warp_m * 32 + mt * 16 + lq;
                af[0] = __float_as_uint(As[arow][kb + lr]);
                af[1] = __float_as_uint(As[arow + 8][kb + lr]);
                af[2] = __float_as_uint(As[arow][kb + 4 + lr]);
                af[3] = __float_as_uint(As[arow + 8][kb + 4 + lr]);
#pragma unroll
                for (int nt = 0; nt < 8; nt++) mma_tf32(acc[mt][nt], af, bf[nt]);
            }
        }
        __syncthreads();
    }

    const int r_base = row0 + warp_m * 32 + lq;
    const int c_base = col0 + warp_n * 64 + lr * 2;
#pragma unroll
    for (int nt = 0; nt < 8; nt++) {
        int c = c_base + nt * 8;
        float2 bv = make_float2(0.f, 0.f);
        if (HASBIAS) bv = *(const float2*)(bias + c);
#pragma unroll
        for (int mt = 0; mt < 2; mt++) {
            int r = r_base + mt * 16;
            if (r < M) {
                float2 o0 = make_float2(acc[mt][nt][0] + bv.x, acc[mt][nt][1] + bv.y);
                *(float2*)(C + (size_t)r * 256 + c) = o0;
            }
            if (r + 8 < M) {
                float2 o1 = make_float2(acc[mt][nt][2] + bv.x, acc[mt][nt][3] + bv.y);
                *(float2*)(C + (size_t)(r + 8) * 256 + c) = o1;
            }
        }
    }
}

// ---------------- edge_attr column sums (once) ----------------
__global__ void esum_kernel(const float* __restrict__ ea) {
    int col = threadIdx.x & 63;
    int rowsPerBlk = blockDim.x >> 6;
    int r0 = blockIdx.x * rowsPerBlk + (threadIdx.x >> 6);
    int rstride = gridDim.x * rowsPerBlk;
    float s = 0.0f;
    for (int r = r0; r < NEDGES; r += rstride) s += ea[(size_t)r * EDIM + col];
    atomicAdd(&g_esum[col], s);
}
__global__ void eloop_kernel(const float* __restrict__ We) {
    int j = threadIdx.x;
    const float inv = 1.0f / (float)NEDGES;
    float acc = 0.0f;
#pragma unroll
    for (int k = 0; k < EDIM; k++) acc = fmaf(g_esum[k] * inv, We[k * 256 + j], acc);
    g_eloop[j] = acc;
}

// ---------------- fused logits: p = exp(att . lrelu(xl[s]+xr[d]+e)), denom += p ----------------
__global__ void logits_kernel(const int* __restrict__ src, const int* __restrict__ dst,
                              const float* __restrict__ att) {
    int gt = blockIdx.x * blockDim.x + threadIdx.x;
    int e = gt >> 5, lane = gt & 31;
    if (e >= ETOT) return;
    int s, d; const float* ep;
    if (e < NEDGES) { s = src[e]; d = dst[e]; ep = g_eproj + (size_t)e * 256; }
    else            { s = e - NEDGES; d = s;  ep = g_eloop; }
    int off = lane * 8;
    const float4* pl = (const float4*)(g_xl + (size_t)s * 256 + off);
    const float4* pr = (const float4*)(g_xr + (size_t)d * 256 + off);
    const float4* pe = (const float4*)(ep + off);
    const float4* pa = (const float4*)(att + off);
    float acc = 0.0f;
#pragma unroll
    for (int q = 0; q < 2; q++) {
        float4 a = pl[q], b = pr[q], c = pe[q], w = pa[q];
        float m;
        m = a.x + b.x + c.x; m = fmaxf(m, 0.2f * m); acc = fmaf(m, w.x, acc);
        m = a.y + b.y + c.y; m = fmaxf(m, 0.2f * m); acc = fmaf(m, w.y, acc);
        m = a.z + b.z + c.z; m = fmaxf(m, 0.2f * m); acc = fmaf(m, w.z, acc);
        m = a.w + b.w + c.w; m = fmaxf(m, 0.2f * m); acc = fmaf(m, w.w, acc);
    }
    acc += __shfl_down_sync(0xffffffffu, acc, 4, 8);
    acc += __shfl_down_sync(0xffffffffu, acc, 2, 8);
    acc += __shfl_down_sync(0xffffffffu, acc, 1, 8);
    if ((lane & 7) == 0) {
        int h = lane >> 3;
        float p = __expf(acc);
        g_logits[(size_t)e * 4 + h] = p;
        atomicAdd(&g_denom[(size_t)d * 4 + h], p);
    }
}

// ---------------- scatter unnormalized: xn[dst] += xl[src] * p ----------------
__global__ void scatter_kernel(const int* __restrict__ src, const int* __restrict__ dst,
                               float* __restrict__ xn) {
    int gt = blockIdx.x * blockDim.x + threadIdx.x;
    int e = gt >> 5, lane = gt & 31;
    if (e >= ETOT) return;
    int s, d;
    if (e < NEDGES) { s = src[e]; d = dst[e]; }
    else            { s = e - NEDGES; d = s; }
    int h = lane >> 3;
    float p = g_logits[(size_t)e * 4 + h];
    const float4* xs = (const float4*)(g_xl + (size_t)s * 256) + lane * 2;
    float4 v0 = xs[0], v1 = xs[1];
    float* bp = xn + (size_t)d * 256 + lane * 8;
    red4(bp,     v0.x * p, v0.y * p, v0.z * p, v0.w * p);
    red4(bp + 4, v1.x * p, v1.y * p, v1.z * p, v1.w * p);
}

// ---------------- normalize + bias + relu in place ----------------
__global__ void relu_bias_kernel(float* __restrict__ x, const float* __restrict__ bias) {
    int i = blockIdx.x * blockDim.x + threadIdx.x;   // over N*64 float4s
    if (i >= NNODES * 64) return;
    int node = i >> 6, c4 = i & 63, h = c4 >> 4;
    float inv = 1.0f / (g_denom[(size_t)node * 4 + h] + 1e-16f);
    float4 v = ((float4*)x)[i];
    float4 b = *(const float4*)(bias + c4 * 4);
    v.x = fmaxf(fmaf(v.x, inv, b.x), 0.f); v.y = fmaxf(fmaf(v.y, inv, b.y), 0.f);
    v.z = fmaxf(fmaf(v.z, inv, b.z), 0.f); v.w = fmaxf(fmaf(v.w, inv, b.w), 0.f);
    ((float4*)x)[i] = v;
}

// ---------------- global mean pool ----------------
__global__ void pool_kernel(const int* __restrict__ batch, const float* __restrict__ xf) {
    int gt = blockIdx.x * blockDim.x + threadIdx.x;
    int node = gt >> 5, lane = gt & 31;
    if (node >= NNODES) return;
    int g = batch[node];
    const float4* xs = (const float4*)(xf + (size_t)node * 256) + lane * 2;
    float4 v0 = xs[0], v1 = xs[1];
    float* bp = g_gsum + (size_t)g * 256 + lane * 8;
    red4(bp,     v0.x, v0.y, v0.z, v0.w);
    red4(bp + 4, v1.x, v1.y, v1.z, v1.w);
    if (lane == 0) atomicAdd(&g_gcnt[g], 1.0f);
}

// ---------------- final MLP ----------------
__global__ __launch_bounds__(128)
void mlp_kernel(const float* __restrict__ Wp1, const float* __restrict__ bp1,
                const float* __restrict__ Wp2, const float* __restrict__ bp2,
                float* __restrict__ out) {
    int g = blockIdx.x;
    __shared__ float pooled[256];
    __shared__ float partial[4];
    float cnt = fmaxf(g_gcnt[g], 1.0f);
    for (int i = threadIdx.x; i < 256; i += 128)
        pooled[i] = g_gsum[(size_t)g * 256 + i] / cnt;
    __syncthreads();
    int j = threadIdx.x;
    float acc = bp1[j];
#pragma unroll 8
    for (int k = 0; k < 256; k++) acc = fmaf(pooled[k], Wp1[k * 128 + j], acc);
    float h = fmaxf(acc, 0.0f) * Wp2[j];
#pragma unroll
    for (int o = 16; o; o >>= 1) h += __shfl_down_sync(0xffffffffu, h, o);
    if ((threadIdx.x & 31) == 0) partial[threadIdx.x >> 5] = h;
    __syncthreads();
    if (threadIdx.x == 0)
        out[g] = partial[0] + partial[1] + partial[2] + partial[3] + bp2[0];
}

// ---------------- launcher ----------------
extern "C" void kernel_launch(void* const* d_in, const int* in_sizes, int n_in,
                              void* d_out, int out_size) {
    const float* x     = (const float*)d_in[0];
    const int*   ei    = (const int*)  d_in[1];
    const float* ea    = (const float*)d_in[2];
    const int*   batch = (const int*)  d_in[3];
    const float* Wl    = (const float*)d_in[4];
    const float* bl    = (const float*)d_in[5];
    const float* Wr    = (const float*)d_in[6];
    const float* br    = (const float*)d_in[7];
    const float* We    = (const float*)d_in[8];
    const float* att   = (const float*)d_in[9];
    const float* bias  = (const float*)d_in[10];
    const float* Wp1   = (const float*)d_in[11];
    const float* bp1   = (const float*)d_in[12];
    const float* Wp2   = (const float*)d_in[13];
    const float* bp2   = (const float*)d_in[14];
    float* out = (float*)d_out;
    const int* src = ei;
    const int* dst = ei + NEDGES;

    float *bufA, *bufB, *xl, *xr, *eproj, *denom, *esum, *gsum, *gcnt;
    cudaGetSymbolAddress((void**)&bufA,  g_bufA);
    cudaGetSymbolAddress((void**)&bufB,  g_bufB);
    cudaGetSymbolAddress((void**)&xl,    g_xl);
    cudaGetSymbolAddress((void**)&xr,    g_xr);
    cudaGetSymbolAddress((void**)&eproj, g_eproj);
    cudaGetSymbolAddress((void**)&denom, g_denom);
    cudaGetSymbolAddress((void**)&esum,  g_esum);
    cudaGetSymbolAddress((void**)&gsum,  g_gsum);
    cudaGetSymbolAddress((void**)&gcnt,  g_gcnt);

    cudaMemsetAsync(esum, 0, EDIM * sizeof(float));
    esum_kernel<<<512, 256>>>(ea);

    const float* xcur = x;
    for (int l = 0; l < NLAYER; l++) {
        float* xn = (l & 1) ? bufB : bufA;
        dim3 gN((NNODES + 127) / 128, 2);
        gemm_mma<256, true><<<gN, 256>>>(xcur, Wl + (size_t)l * 256 * 256, bl + l * 256, xl, NNODES);
        gemm_mma<256, true><<<gN, 256>>>(xcur, Wr + (size_t)l * 256 * 256, br + l * 256, xr, NNODES);
        dim3 gE((NEDGES + 127) / 128, 2);
        gemm_mma<64, false><<<gE, 256>>>(ea, We + (size_t)l * 64 * 256, nullptr, eproj, NEDGES);
        eloop_kernel<<<1, 256>>>(We + (size_t)l * 64 * 256);

        cudaMemsetAsync(denom, 0, (size_t)NNODES * 4 * sizeof(float));
        cudaMemsetAsync(xn, 0, (size_t)NNODES * 256 * sizeof(float));

        logits_kernel<<<(ETOT * 32) / 256, 256>>>(src, dst, att + l * 256);
        scatter_kernel<<<(ETOT * 32) / 256, 256>>>(src, dst, xn);
        relu_bias_kernel<<<(NNODES * 64) / 256, 256>>>(xn, bias + l * 256);
        xcur = xn;
    }

    cudaMemsetAsync(gsum, 0, (size_t)GDIM * 256 * sizeof(float));
    cudaMemsetAsync(gcnt, 0, GDIM * sizeof(float));
    pool_kernel<<<(NNODES * 32 + 255) / 256, 256>>>(batch, xcur);
    mlp_kernel<<<GDIM, 128>>>(Wp1, bp1, Wp2, bp2, out);
}

// round 4
// speedup vs baseline: 2.4970x; 1.3668x over previous
#include <cuda_runtime.h>
#include <cuda_bf16.h>
#include <cstdint>

#define NNODES 100000
#define NEDGES 300000
#define GDIM   2048
#define HIDDIM 256
#define EDIM   64
#define NLAYER 3
#define NBLK   ((NNODES + 255) / 256)   // 391

// ---------------- static device scratch ----------------
__device__ float g_bufA[(size_t)NNODES * HIDDIM];
__device__ float g_bufB[(size_t)NNODES * HIDDIM];
__device__ float g_xl[(size_t)NNODES * HIDDIM];
__device__ float g_xr[(size_t)NNODES * HIDDIM];
__device__ float g_eproj[(size_t)NEDGES * HIDDIM];
__device__ float g_eloop[HIDDIM];
__device__ float g_esum[EDIM];
__device__ float g_gsum[(size_t)GDIM * HIDDIM];
__device__ float g_gcnt[GDIM];
// CSR (dst-sorted edges)
__device__ int g_cnt[NNODES];
__device__ int g_bsum[512];
__device__ int g_rowptr[NNODES + 1];
__device__ int g_woff[NNODES];
__device__ int g_ssrc[NEDGES];
__device__ int g_seid[NEDGES];

// ---------------- helpers ----------------
__device__ __forceinline__ void red4(float* p, float a, float b, float c, float d) {
    asm volatile("red.global.add.v4.f32 [%0], {%1,%2,%3,%4};"
                 :: "l"(p), "f"(a), "f"(b), "f"(c), "f"(d) : "memory");
}
__device__ __forceinline__ void mma_tf32(float* c, const uint32_t* a, const uint32_t* b) {
    asm volatile("mma.sync.aligned.m16n8k8.row.col.f32.tf32.tf32.f32 "
                 "{%0,%1,%2,%3}, {%4,%5,%6,%7}, {%8,%9}, {%0,%1,%2,%3};"
                 : "+f"(c[0]), "+f"(c[1]), "+f"(c[2]), "+f"(c[3])
                 : "r"(a[0]), "r"(a[1]), "r"(a[2]), "r"(a[3]), "r"(b[0]), "r"(b[1]));
}

// ---------------- tf32 tensor-core GEMM (unchanged from R3) ----------------
template<int K, bool HASBIAS>
__global__ __launch_bounds__(256)
void gemm_mma(const float* __restrict__ A, const float* __restrict__ W,
              const float* __restrict__ bias, float* __restrict__ C, int M) {
    __shared__ __align__(16) float As[128][36];
    __shared__ __align__(16) float Bs[32][136];
    const int tid = threadIdx.x, warp = tid >> 5, lane = tid & 31;
    const int warp_m = warp & 3, warp_n = warp >> 2;
    const int row0 = blockIdx.x * 128, col0 = blockIdx.y * 128;
    const int lq = lane >> 2, lr = lane & 3;

    float acc[2][8][4];
#pragma unroll
    for (int mt = 0; mt < 2; mt++)
#pragma unroll
        for (int nt = 0; nt < 8; nt++)
#pragma unroll
            for (int i = 0; i < 4; i++) acc[mt][nt][i] = 0.0f;

    for (int k0 = 0; k0 < K; k0 += 32) {
#pragma unroll
        for (int i = 0; i < 4; i++) {
            int idx = tid + i * 256;
            int r = idx >> 3, q = idx & 7;
            int ar = row0 + r; if (ar >= M) ar = M - 1;
            *(float4*)&As[r][q * 4] = *(const float4*)(A + (size_t)ar * K + k0 + q * 4);
        }
#pragma unroll
        for (int i = 0; i < 4; i++) {
            int idx = tid + i * 256;
            int r = idx >> 5, q = idx & 31;
            *(float4*)&Bs[r][q * 4] = *(const float4*)(W + (size_t)(k0 + r) * 256 + col0 + q * 4);
        }
        __syncthreads();
#pragma unroll
        for (int ks = 0; ks < 4; ks++) {
            const int kb = ks * 8;
            uint32_t bf[8][2];
            const int brow = kb + lr, bcol = warp_n * 64 + lq;
#pragma unroll
            for (int nt = 0; nt < 8; nt++) {
                bf[nt][0] = __float_as_uint(Bs[brow][bcol + nt * 8]);
                bf[nt][1] = __float_as_uint(Bs[brow + 4][bcol + nt * 8]);
            }
#pragma unroll
            for (int mt = 0; mt < 2; mt++) {
                uint32_t af[4];
                const int arow = warp_m * 32 + mt * 16 + lq;
                af[0] = __float_as_uint(As[arow][kb + lr]);
                af[1] = __float_as_uint(As[arow + 8][kb + lr]);
                af[2] = __float_as_uint(As[arow][kb + 4 + lr]);
                af[3] = __float_as_uint(As[arow + 8][kb + 4 + lr]);
#pragma unroll
                for (int nt = 0; nt < 8; nt++) mma_tf32(acc[mt][nt], af, bf[nt]);
            }
        }
        __syncthreads();
    }

    const int r_base = row0 + warp_m * 32 + lq;
    const int c_base = col0 + warp_n * 64 + lr * 2;
#pragma unroll
    for (int nt = 0; nt < 8; nt++) {
        int c = c_base + nt * 8;
        float2 bv = make_float2(0.f, 0.f);
        if (HASBIAS) bv = *(const float2*)(bias + c);
#pragma unroll
        for (int mt = 0; mt < 2; mt++) {
            int r = r_base + mt * 16;
            if (r < M) {
                float2 o0 = make_float2(acc[mt][nt][0] + bv.x, acc[mt][nt][1] + bv.y);
                *(float2*)(C + (size_t)r * 256 + c) = o0;
            }
            if (r + 8 < M) {
                float2 o1 = make_float2(acc[mt][nt][2] + bv.x, acc[mt][nt][3] + bv.y);
                *(float2*)(C + (size_t)(r + 8) * 256 + c) = o1;
            }
        }
    }
}

// ---------------- CSR build (once per launch) ----------------
__global__ void hist_kernel(const int* __restrict__ dst) {
    int e = blockIdx.x * blockDim.x + threadIdx.x;
    if (e < NEDGES) atomicAdd(&g_cnt[dst[e]], 1);
}
__global__ void blocksum_kernel() {
    int i = blockIdx.x * 256 + threadIdx.x;
    int v = (i < NNODES) ? g_cnt[i] : 0;
    __shared__ int ws[8];
#pragma unroll
    for (int o = 16; o; o >>= 1) v += __shfl_down_sync(0xffffffffu, v, o);
    if ((threadIdx.x & 31) == 0) ws[threadIdx.x >> 5] = v;
    __syncthreads();
    if (threadIdx.x == 0) {
        int s = 0;
#pragma unroll
        for (int j = 0; j < 8; j++) s += ws[j];
        g_bsum[blockIdx.x] = s;
    }
}
__global__ void scanb_kernel() {   // 1 block, 512 threads; exclusive scan of g_bsum
    __shared__ int sm[512];
    int i = threadIdx.x;
    int v = (i < NBLK) ? g_bsum[i] : 0;
    sm[i] = v;
    __syncthreads();
    for (int s = 1; s < 512; s <<= 1) {
        int t = (i >= s) ? sm[i - s] : 0;
        __syncthreads();
        sm[i] += t;
        __syncthreads();
    }
    if (i < NBLK) g_bsum[i] = sm[i] - v;
}
__global__ void rowptr_kernel() {
    int tid = threadIdx.x;
    int i = blockIdx.x * 256 + tid;
    int v = (i < NNODES) ? g_cnt[i] : 0;
    __shared__ int sm[256];
    sm[tid] = v;
    __syncthreads();
    for (int s = 1; s < 256; s <<= 1) {
        int t = (tid >= s) ? sm[tid - s] : 0;
        __syncthreads();
        sm[tid] += t;
        __syncthreads();
    }
    int ex = sm[tid] - v + g_bsum[blockIdx.x];
    if (i < NNODES) { g_rowptr[i] = ex; g_woff[i] = ex; }
    if (i == NNODES - 1) g_rowptr[NNODES] = NEDGES;
}
__global__ void fill_kernel(const int* __restrict__ src, const int* __restrict__ dst) {
    int e = blockIdx.x * blockDim.x + threadIdx.x;
    if (e >= NEDGES) return;
    int d = dst[e];
    int pos = atomicAdd(&g_woff[d], 1);
    g_ssrc[pos] = src[e];
    g_seid[pos] = e;
}

// ---------------- edge_attr column sums (once) ----------------
__global__ void esum_kernel(const float* __restrict__ ea) {
    int col = threadIdx.x & 63;
    int rowsPerBlk = blockDim.x >> 6;
    int r0 = blockIdx.x * rowsPerBlk + (threadIdx.x >> 6);
    int rstride = gridDim.x * rowsPerBlk;
    float s = 0.0f;
    for (int r = r0; r < NEDGES; r += rstride) s += ea[(size_t)r * EDIM + col];
    atomicAdd(&g_esum[col], s);
}
__global__ void eloop_kernel(const float* __restrict__ We) {
    int j = threadIdx.x;
    const float inv = 1.0f / (float)NEDGES;
    float acc = 0.0f;
#pragma unroll
    for (int k = 0; k < EDIM; k++) acc = fmaf(g_esum[k] * inv, We[k * 256 + j], acc);
    g_eloop[j] = acc;
}

// ---------------- fused GAT edge phase: warp per dst node ----------------
// out[d] = relu( (sum_e p_e * xl[src_e]) / (sum_e p_e) + bias ),
// p_e = exp( att . lrelu(xl[src_e] + xr[d] + eproj[e]) ); self-loop included.
__global__ __launch_bounds__(256)
void fused_gat_kernel(const float* __restrict__ att, const float* __restrict__ bias,
                      float* __restrict__ xn) {
    int gt = blockIdx.x * blockDim.x + threadIdx.x;
    int d = gt >> 5, lane = gt & 31;
    if (d >= NNODES) return;
    const int off = lane * 8;

    float4 xr0 = *(const float4*)(g_xr + (size_t)d * 256 + off);
    float4 xr1 = *(const float4*)(g_xr + (size_t)d * 256 + off + 4);
    float4 at0 = *(const float4*)(att + off);
    float4 at1 = *(const float4*)(att + off + 4);

    float acc[8];
    float denom;
    // ---- self loop: src = d, edge feature = eloop ----
    {
        float4 a0 = *(const float4*)(g_xl + (size_t)d * 256 + off);
        float4 a1 = *(const float4*)(g_xl + (size_t)d * 256 + off + 4);
        float4 e0 = *(const float4*)(g_eloop + off);
        float4 e1 = *(const float4*)(g_eloop + off + 4);
        float t = 0.0f, m;
        m = a0.x + xr0.x + e0.x; m = fmaxf(m, 0.2f * m); t = fmaf(m, at0.x, t);
        m = a0.y + xr0.y + e0.y; m = fmaxf(m, 0.2f * m); t = fmaf(m, at0.y, t);
        m = a0.z + xr0.z + e0.z; m = fmaxf(m, 0.2f * m); t = fmaf(m, at0.z, t);
        m = a0.w + xr0.w + e0.w; m = fmaxf(m, 0.2f * m); t = fmaf(m, at0.w, t);
        m = a1.x + xr1.x + e1.x; m = fmaxf(m, 0.2f * m); t = fmaf(m, at1.x, t);
        m = a1.y + xr1.y + e1.y; m = fmaxf(m, 0.2f * m); t = fmaf(m, at1.y, t);
        m = a1.z + xr1.z + e1.z; m = fmaxf(m, 0.2f * m); t = fmaf(m, at1.z, t);
        m = a1.w + xr1.w + e1.w; m = fmaxf(m, 0.2f * m); t = fmaf(m, at1.w, t);
        t += __shfl_down_sync(0xffffffffu, t, 4, 8);
        t += __shfl_down_sync(0xffffffffu, t, 2, 8);
        t += __shfl_down_sync(0xffffffffu, t, 1, 8);
        float p = __expf(__shfl_sync(0xffffffffu, t, 0, 8));
        denom = p;
        acc[0] = p * a0.x; acc[1] = p * a0.y; acc[2] = p * a0.z; acc[3] = p * a0.w;
        acc[4] = p * a1.x; acc[5] = p * a1.y; acc[6] = p * a1.z; acc[7] = p * a1.w;
    }
    // ---- real edges (dst-sorted CSR) ----
    const int beg = g_rowptr[d], end = g_rowptr[d + 1];
    for (int i = beg; i < end; i++) {
        int s = g_ssrc[i];
        int e = g_seid[i];
        float4 a0 = *(const float4*)(g_xl + (size_t)s * 256 + off);
        float4 a1 = *(const float4*)(g_xl + (size_t)s * 256 + off + 4);
        float4 e0 = *(const float4*)(g_eproj + (size_t)e * 256 + off);
        float4 e1 = *(const float4*)(g_eproj + (size_t)e * 256 + off + 4);
        float t = 0.0f, m;
        m = a0.x + xr0.x + e0.x; m = fmaxf(m, 0.2f * m); t = fmaf(m, at0.x, t);
        m = a0.y + xr0.y + e0.y; m = fmaxf(m, 0.2f * m); t = fmaf(m, at0.y, t);
        m = a0.z + xr0.z + e0.z; m = fmaxf(m, 0.2f * m); t = fmaf(m, at0.z, t);
        m = a0.w + xr0.w + e0.w; m = fmaxf(m, 0.2f * m); t = fmaf(m, at0.w, t);
        m = a1.x + xr1.x + e1.x; m = fmaxf(m, 0.2f * m); t = fmaf(m, at1.x, t);
        m = a1.y + xr1.y + e1.y; m = fmaxf(m, 0.2f * m); t = fmaf(m, at1.y, t);
        m = a1.z + xr1.z + e1.z; m = fmaxf(m, 0.2f * m); t = fmaf(m, at1.z, t);
        m = a1.w + xr1.w + e1.w; m = fmaxf(m, 0.2f * m); t = fmaf(m, at1.w, t);
        t += __shfl_down_sync(0xffffffffu, t, 4, 8);
        t += __shfl_down_sync(0xffffffffu, t, 2, 8);
        t += __shfl_down_sync(0xffffffffu, t, 1, 8);
        float p = __expf(__shfl_sync(0xffffffffu, t, 0, 8));
        denom += p;
        acc[0] = fmaf(p, a0.x, acc[0]); acc[1] = fmaf(p, a0.y, acc[1]);
        acc[2] = fmaf(p, a0.z, acc[2]); acc[3] = fmaf(p, a0.w, acc[3]);
        acc[4] = fmaf(p, a1.x, acc[4]); acc[5] = fmaf(p, a1.y, acc[5]);
        acc[6] = fmaf(p, a1.z, acc[6]); acc[7] = fmaf(p, a1.w, acc[7]);
    }
    float inv = 1.0f / (denom + 1e-16f);
    float4 b0 = *(const float4*)(bias + off);
    float4 b1 = *(const float4*)(bias + off + 4);
    float4 o0, o1;
    o0.x = fmaxf(fmaf(acc[0], inv, b0.x), 0.f); o0.y = fmaxf(fmaf(acc[1], inv, b0.y), 0.f);
    o0.z = fmaxf(fmaf(acc[2], inv, b0.z), 0.f); o0.w = fmaxf(fmaf(acc[3], inv, b0.w), 0.f);
    o1.x = fmaxf(fmaf(acc[4], inv, b1.x), 0.f); o1.y = fmaxf(fmaf(acc[5], inv, b1.y), 0.f);
    o1.z = fmaxf(fmaf(acc[6], inv, b1.z), 0.f); o1.w = fmaxf(fmaf(acc[7], inv, b1.w), 0.f);
    *(float4*)(xn + (size_t)d * 256 + off) = o0;
    *(float4*)(xn + (size_t)d * 256 + off + 4) = o1;
}

// ---------------- global mean pool ----------------
__global__ void pool_kernel(const int* __restrict__ batch, const float* __restrict__ xf) {
    int gt = blockIdx.x * blockDim.x + threadIdx.x;
    int node = gt >> 5, lane = gt & 31;
    if (node >= NNODES) return;
    int g = batch[node];
    const float4* xs = (const float4*)(xf + (size_t)node * 256) + lane * 2;
    float4 v0 = xs[0], v1 = xs[1];
    float* bp = g_gsum + (size_t)g * 256 + lane * 8;
    red4(bp,     v0.x, v0.y, v0.z, v0.w);
    red4(bp + 4, v1.x, v1.y, v1.z, v1.w);
    if (lane == 0) atomicAdd(&g_gcnt[g], 1.0f);
}

// ---------------- final MLP ----------------
__global__ __launch_bounds__(128)
void mlp_kernel(const float* __restrict__ Wp1, const float* __restrict__ bp1,
                const float* __restrict__ Wp2, const float* __restrict__ bp2,
                float* __restrict__ out) {
    int g = blockIdx.x;
    __shared__ float pooled[256];
    __shared__ float partial[4];
    float cnt = fmaxf(g_gcnt[g], 1.0f);
    for (int i = threadIdx.x; i < 256; i += 128)
        pooled[i] = g_gsum[(size_t)g * 256 + i] / cnt;
    __syncthreads();
    int j = threadIdx.x;
    float acc = bp1[j];
#pragma unroll 8
    for (int k = 0; k < 256; k++) acc = fmaf(pooled[k], Wp1[k * 128 + j], acc);
    float h = fmaxf(acc, 0.0f) * Wp2[j];
#pragma unroll
    for (int o = 16; o; o >>= 1) h += __shfl_down_sync(0xffffffffu, h, o);
    if ((threadIdx.x & 31) == 0) partial[threadIdx.x >> 5] = h;
    __syncthreads();
    if (threadIdx.x == 0)
        out[g] = partial[0] + partial[1] + partial[2] + partial[3] + bp2[0];
}

// ---------------- launcher ----------------
extern "C" void kernel_launch(void* const* d_in, const int* in_sizes, int n_in,
                              void* d_out, int out_size) {
    const float* x     = (const float*)d_in[0];
    const int*   ei    = (const int*)  d_in[1];
    const float* ea    = (const float*)d_in[2];
    const int*   batch = (const int*)  d_in[3];
    const float* Wl    = (const float*)d_in[4];
    const float* bl    = (const float*)d_in[5];
    const float* Wr    = (const float*)d_in[6];
    const float* br    = (const float*)d_in[7];
    const float* We    = (const float*)d_in[8];
    const float* att   = (const float*)d_in[9];
    const float* bias  = (const float*)d_in[10];
    const float* Wp1   = (const float*)d_in[11];
    const float* bp1   = (const float*)d_in[12];
    const float* Wp2   = (const float*)d_in[13];
    const float* bp2   = (const float*)d_in[14];
    float* out = (float*)d_out;
    const int* src = ei;
    const int* dst = ei + NEDGES;

    float *bufA, *bufB, *xl, *xr, *eproj, *esum, *gsum, *gcnt;
    int* cnt;
    cudaGetSymbolAddress((void**)&bufA,  g_bufA);
    cudaGetSymbolAddress((void**)&bufB,  g_bufB);
    cudaGetSymbolAddress((void**)&xl,    g_xl);
    cudaGetSymbolAddress((void**)&xr,    g_xr);
    cudaGetSymbolAddress((void**)&eproj, g_eproj);
    cudaGetSymbolAddress((void**)&esum,  g_esum);
    cudaGetSymbolAddress((void**)&gsum,  g_gsum);
    cudaGetSymbolAddress((void**)&gcnt,  g_gcnt);
    cudaGetSymbolAddress((void**)&cnt,   g_cnt);

    // ---- CSR build (graph topology is constant) ----
    cudaMemsetAsync(cnt, 0, NNODES * sizeof(int));
    hist_kernel<<<(NEDGES + 255) / 256, 256>>>(dst);
    blocksum_kernel<<<NBLK, 256>>>();
    scanb_kernel<<<1, 512>>>();
    rowptr_kernel<<<NBLK, 256>>>();
    fill_kernel<<<(NEDGES + 255) / 256, 256>>>(src, dst);

    cudaMemsetAsync(esum, 0, EDIM * sizeof(float));
    esum_kernel<<<512, 256>>>(ea);

    const float* xcur = x;
    for (int l = 0; l < NLAYER; l++) {
        float* xn = (l & 1) ? bufB : bufA;
        dim3 gN((NNODES + 127) / 128, 2);
        gemm_mma<256, true><<<gN, 256>>>(xcur, Wl + (size_t)l * 256 * 256, bl + l * 256, xl, NNODES);
        gemm_mma<256, true><<<gN, 256>>>(xcur, Wr + (size_t)l * 256 * 256, br + l * 256, xr, NNODES);
        dim3 gE((NEDGES + 127) / 128, 2);
        gemm_mma<64, false><<<gE, 256>>>(ea, We + (size_t)l * 64 * 256, nullptr, eproj, NEDGES);
        eloop_kernel<<<1, 256>>>(We + (size_t)l * 64 * 256);

        fused_gat_kernel<<<(NNODES * 32 + 255) / 256, 256>>>(att + l * 256, bias + l * 256, xn);
        xcur = xn;
    }

    cudaMemsetAsync(gsum, 0, (size_t)GDIM * 256 * sizeof(float));
    cudaMemsetAsync(gcnt, 0, GDIM * sizeof(float));
    pool_kernel<<<(NNODES * 32 + 255) / 256, 256>>>(batch, xcur);
    mlp_kernel<<<GDIM, 128>>>(Wp1, bp1, Wp2, bp2, out);
}